// round 7
// baseline (speedup 1.0000x reference)
#include <cuda_runtime.h>

#define D     512
#define NH    8
#define HD    64
#define NI_   3
#define B_    4
#define NQ    8192
#define NKV   4096
#define MQ    (B_ * NQ)   // 32768

// Scratch (static device arrays; no allocation at runtime).
__device__ float g_q[MQ * D];                    // q, overwritten in-place with u by combine
__device__ float g_kv[NI_ * B_ * NH * HD * HD];  // per (i,b,h) 64x64 kv matrices
__device__ float g_ksum[NI_ * B_ * NH * HD];     // per (i,b,h) 64-vector k_sum
__device__ int   g_mask_u8;                      // 1 if masks are byte-packed bools

// ---------------------------------------------------------------------------
// Zero accumulators + detect mask encoding (word-sized int32/float32 vs uint8).
__global__ void zero_kernel(const unsigned int* __restrict__ mask_words) {
    int idx = blockIdx.x * blockDim.x + threadIdx.x;
    if (idx < NI_ * B_ * NH * HD * HD) g_kv[idx] = 0.0f;
    if (idx < NI_ * B_ * NH * HD)      g_ksum[idx] = 0.0f;
    if (blockIdx.x == 0 && threadIdx.x == 0) {
        // If masks were widened to int32 (0/1) or float32 (0.0/1.0), every
        // 32-bit word is 0, 1, or 0x3F800000. Byte-packed random bools make
        // other word values with overwhelming probability.
        int u8 = 0;
        for (int i = 0; i < 1024; i++) {
            unsigned w = mask_words[i];
            if (w != 0u && w != 1u && w != 0x3F800000u) { u8 = 1; break; }
        }
        g_mask_u8 = u8;
    }
}

// ---------------------------------------------------------------------------
// Q projection: C[m, n0+c] = sum_k x[m,k] * Wq[n0+c,k] + bq, then rowwise
// softmax over the 64 columns of the head (one head == one 64-col tile).
__global__ __launch_bounds__(256)
void qproj_kernel(const float* __restrict__ A, const float* __restrict__ W,
                  const float* __restrict__ bias)
{
    __shared__ float sm[128 * 65];                    // 33.3 KB, reused by epilogue
    float (*As)[33] = (float (*)[33])sm;              // [128][33]
    float (*Ws)[33] = (float (*)[33])(sm + 128 * 33); // [64][33]
    const int tid = threadIdx.x;
    const int tx = tid & 15, ty = tid >> 4;
    const int m0 = blockIdx.x * 128;
    const int n0 = blockIdx.y * 64;

    float acc[8][4];
#pragma unroll
    for (int i = 0; i < 8; i++)
#pragma unroll
        for (int j = 0; j < 4; j++) acc[i][j] = 0.0f;

    const int lr = tid >> 3;          // 0..31
    const int lk = (tid & 7) << 2;    // 0..28 step 4
    for (int k0 = 0; k0 < D; k0 += 32) {
#pragma unroll
        for (int it = 0; it < 4; it++) {
            float4 v = *(const float4*)(A + (size_t)(m0 + lr + it * 32) * D + k0 + lk);
            float* p = &As[lr + it * 32][lk];
            p[0] = v.x; p[1] = v.y; p[2] = v.z; p[3] = v.w;
        }
#pragma unroll
        for (int it = 0; it < 2; it++) {
            float4 v = *(const float4*)(W + (size_t)(n0 + lr + it * 32) * D + k0 + lk);
            float* p = &Ws[lr + it * 32][lk];
            p[0] = v.x; p[1] = v.y; p[2] = v.z; p[3] = v.w;
        }
        __syncthreads();
#pragma unroll
        for (int kk = 0; kk < 32; kk++) {
            float a[8], bb[4];
#pragma unroll
            for (int i = 0; i < 8; i++) a[i] = As[ty + 16 * i][kk];
#pragma unroll
            for (int j = 0; j < 4; j++) bb[j] = Ws[tx + 16 * j][kk];
#pragma unroll
            for (int i = 0; i < 8; i++)
#pragma unroll
                for (int j = 0; j < 4; j++) acc[i][j] = fmaf(a[i], bb[j], acc[i][j]);
        }
        __syncthreads();
    }

    float (*Cs)[65] = (float (*)[65])sm;
#pragma unroll
    for (int j = 0; j < 4; j++) {
        float bv = bias[n0 + tx + 16 * j];
#pragma unroll
        for (int i = 0; i < 8; i++) Cs[ty + 16 * i][tx + 16 * j] = acc[i][j] + bv;
    }
    __syncthreads();

    const int warp = tid >> 5, lane = tid & 31;
    for (int r = warp; r < 128; r += 8) {
        float v0 = Cs[r][lane], v1 = Cs[r][lane + 32];
        float mx = fmaxf(v0, v1);
#pragma unroll
        for (int o = 16; o; o >>= 1) mx = fmaxf(mx, __shfl_xor_sync(0xffffffffu, mx, o));
        float e0 = __expf(v0 - mx), e1 = __expf(v1 - mx);
        float s = e0 + e1;
#pragma unroll
        for (int o = 16; o; o >>= 1) s += __shfl_xor_sync(0xffffffffu, s, o);
        float inv = 1.0f / s;
        size_t base = (size_t)(m0 + r) * D + n0;
        g_q[base + lane]      = e0 * inv;
        g_q[base + lane + 32] = e1 * inv;
    }
}

// ---------------------------------------------------------------------------
// K/V projection for one (i, b, head, 128-row tile):
//  - GEMM: Ck[128,64], Cv[128,64]
//  - softmax rows of Ck, zero masked rows
//  - atomically accumulate k_sum (col sums) and kv = Ck^T @ Cv
// k and v are never written to global memory.
__global__ __launch_bounds__(256)
void kvproj_kernel(const float* __restrict__ emb0, const float* __restrict__ emb1,
                   const float* __restrict__ emb2,
                   const float* __restrict__ Wk, const float* __restrict__ bk,
                   const float* __restrict__ Wv, const float* __restrict__ bv,
                   const void* __restrict__ mask0,
                   const void* __restrict__ mask1,
                   const void* __restrict__ mask2)
{
    extern __shared__ float sm[];                     // 66560 B dynamic
    float (*As)[33] = (float (*)[33])sm;              // [128][33]
    float (*Ws)[33] = (float (*)[33])(sm + 128 * 33); // [128][33]

    const int tid = threadIdx.x;
    const int tx = tid & 15, ty = tid >> 4;
    const int s0 = blockIdx.x * 128;
    const int h  = blockIdx.y;
    const int z  = blockIdx.z;
    const int ii = z >> 2;        // input index 0..2  (B_=4)
    const int b  = z & 3;

    const float* emb = (ii == 0) ? emb0 : (ii == 1) ? emb1 : emb2;
    const void* mask = (ii == 0) ? mask0 : (ii == 1) ? mask1 : mask2;
    const float* A   = emb + (size_t)b * NKV * D;
    const float* Wkh = Wk + (size_t)ii * D * D + (size_t)h * HD * D;
    const float* Wvh = Wv + (size_t)ii * D * D + (size_t)h * HD * D;
    const float* bkh = bk + ii * D + h * HD;
    const float* bvh = bv + ii * D + h * HD;
    const int mask_u8 = g_mask_u8;

    float acc[8][8];
#pragma unroll
    for (int i = 0; i < 8; i++)
#pragma unroll
        for (int j = 0; j < 8; j++) acc[i][j] = 0.0f;

    const int lr = tid >> 3, lk = (tid & 7) << 2;
    for (int k0 = 0; k0 < D; k0 += 32) {
#pragma unroll
        for (int it = 0; it < 4; it++) {
            float4 v = *(const float4*)(A + (size_t)(s0 + lr + it * 32) * D + k0 + lk);
            float* p = &As[lr + it * 32][lk];
            p[0] = v.x; p[1] = v.y; p[2] = v.z; p[3] = v.w;
        }
#pragma unroll
        for (int it = 0; it < 4; it++) {
            int n = lr + it * 32;  // 0..127 : 0-63 -> Wk rows, 64-127 -> Wv rows
            const float* Wp = (n < 64) ? (Wkh + (size_t)n * D) : (Wvh + (size_t)(n - 64) * D);
            float4 v = *(const float4*)(Wp + k0 + lk);
            float* p = &Ws[n][lk];
            p[0] = v.x; p[1] = v.y; p[2] = v.z; p[3] = v.w;
        }
        __syncthreads();
#pragma unroll
        for (int kk = 0; kk < 32; kk++) {
            float a[8], bb[8];
#pragma unroll
            for (int i = 0; i < 8; i++) a[i] = As[ty + 16 * i][kk];
#pragma unroll
            for (int j = 0; j < 8; j++) bb[j] = Ws[tx + 16 * j][kk];
#pragma unroll
            for (int i = 0; i < 8; i++)
#pragma unroll
                for (int j = 0; j < 8; j++) acc[i][j] = fmaf(a[i], bb[j], acc[i][j]);
        }
        __syncthreads();
    }

    // Epilogue staging: Ks [128][65] at 0, Vs [128][65] at +8320 floats
    float (*Ks)[65] = (float (*)[65])sm;
    float (*Vs)[65] = (float (*)[65])(sm + 8320);
#pragma unroll
    for (int j = 0; j < 8; j++) {
        int c = tx + 16 * j;       // 0..127
        float bvl = (c < 64) ? bkh[c] : bvh[c - 64];
#pragma unroll
        for (int i = 0; i < 8; i++) {
            float val = acc[i][j] + bvl;
            if (c < 64) Ks[ty + 16 * i][c]      = val;
            else        Vs[ty + 16 * i][c - 64] = val;
        }
    }
    __syncthreads();

    // Per-row softmax on Ks, then zero masked rows (softmax then mask, per reference)
    const int warp = tid >> 5, lane = tid & 31;
    for (int r = warp; r < 128; r += 8) {
        float v0 = Ks[r][lane], v1 = Ks[r][lane + 32];
        float mx = fmaxf(v0, v1);
#pragma unroll
        for (int o = 16; o; o >>= 1) mx = fmaxf(mx, __shfl_xor_sync(0xffffffffu, mx, o));
        float e0 = __expf(v0 - mx), e1 = __expf(v1 - mx);
        float s = e0 + e1;
#pragma unroll
        for (int o = 16; o; o >>= 1) s += __shfl_xor_sync(0xffffffffu, s, o);
        float inv = 1.0f / s;
        size_t midx = (size_t)b * NKV + s0 + r;
        bool keep;
        if (mask_u8) keep = ((const unsigned char*)mask)[midx] != 0;
        else         keep = ((const unsigned int*)mask)[midx]  != 0u;  // int32 or fp32 0/1
        float mval = keep ? inv : 0.0f;
        Ks[r][lane]      = e0 * mval;
        Ks[r][lane + 32] = e1 * mval;
    }
    __syncthreads();

    // k_sum partial (4 partial sums per column, atomically merged)
    {
        int c = tid & 63, qg = tid >> 6;
        float s = 0.0f;
#pragma unroll
        for (int r = 0; r < 32; r++) s += Ks[qg * 32 + r][c];
        atomicAdd(&g_ksum[((ii * B_ + b) * NH + h) * HD + c], s);
    }

    // kv partial: P[d][e] = sum_r Ks[r][d] * Vs[r][e], 4x4 per thread
    {
        float p[4][4];
#pragma unroll
        for (int a2 = 0; a2 < 4; a2++)
#pragma unroll
            for (int b2 = 0; b2 < 4; b2++) p[a2][b2] = 0.0f;
        for (int r = 0; r < 128; r++) {
            float kd[4], ve[4];
#pragma unroll
            for (int a2 = 0; a2 < 4; a2++) kd[a2] = Ks[r][ty + 16 * a2];
#pragma unroll
            for (int b2 = 0; b2 < 4; b2++) ve[b2] = Vs[r][tx + 16 * b2];
#pragma unroll
            for (int a2 = 0; a2 < 4; a2++)
#pragma unroll
                for (int b2 = 0; b2 < 4; b2++) p[a2][b2] = fmaf(kd[a2], ve[b2], p[a2][b2]);
        }
        float* kvp = g_kv + (size_t)((ii * B_ + b) * NH + h) * HD * HD;
#pragma unroll
        for (int a2 = 0; a2 < 4; a2++)
#pragma unroll
            for (int b2 = 0; b2 < 4; b2++)
                atomicAdd(&kvp[(ty + 16 * a2) * HD + tx + 16 * b2], p[a2][b2]);
    }
}

// ---------------------------------------------------------------------------
// Combine: u = (q + sum_i (q @ kv_i) * d_inv_i) / NI, in-place over g_q.
__global__ __launch_bounds__(256)
void combine_kernel()
{
    extern __shared__ float sm[];        // 84224 B dynamic
    float* kvs   = sm;                   // 3*64*64 = 12288
    float* qs    = sm + 12288;           // 128*64  = 8192
    float* ksums = sm + 20480;           // 3*64    = 192
    float* sdinv = sm + 20672;           // 3*128   = 384
    const int tid = threadIdx.x;
    const int m0 = blockIdx.x * 128;
    const int h  = blockIdx.y;
    const int b  = blockIdx.z;

    for (int idx = tid; idx < 3072; idx += 256) {
        int i = idx >> 10;
        int off = (idx & 1023) << 2;
        float4 v = *(const float4*)(g_kv + (size_t)((i * B_ + b) * NH + h) * 4096 + off);
        float* p = kvs + i * 4096 + off;
        p[0] = v.x; p[1] = v.y; p[2] = v.z; p[3] = v.w;
    }
    for (int idx = tid; idx < 2048; idx += 256) {
        int r = idx >> 4;
        int c4 = (idx & 15) << 2;
        float4 v = *(const float4*)(g_q + (size_t)(b * NQ + m0 + r) * D + h * HD + c4);
        float* p = qs + r * 64 + c4;
        p[0] = v.x; p[1] = v.y; p[2] = v.z; p[3] = v.w;
    }
    if (tid < 192) {
        int i = tid >> 6, c = tid & 63;
        ksums[tid] = g_ksum[((i * B_ + b) * NH + h) * HD + c];
    }
    __syncthreads();

    for (int idx = tid; idx < 384; idx += 256) {
        int r = idx & 127, i = idx >> 7;
        float s = 0.0f;
#pragma unroll
        for (int d = 0; d < 64; d++) s += qs[r * 64 + d] * ksums[i * 64 + d];
        sdinv[i * 128 + r] = 1.0f / s;
    }
    __syncthreads();

    const int c  = tid & 63;
    const int rg = tid >> 6;
    for (int rc = 0; rc < 32; rc += 8) {
        const int r0 = rg * 32 + rc;
        float y[8];
#pragma unroll
        for (int q2 = 0; q2 < 8; q2++) y[q2] = qs[(r0 + q2) * 64 + c];
#pragma unroll
        for (int i = 0; i < 3; i++) {
            float s[8];
#pragma unroll
            for (int q2 = 0; q2 < 8; q2++) s[q2] = 0.0f;
            for (int d = 0; d < 64; d++) {
                float kvv = kvs[i * 4096 + d * 64 + c];
#pragma unroll
                for (int q2 = 0; q2 < 8; q2++)
                    s[q2] = fmaf(qs[(r0 + q2) * 64 + d], kvv, s[q2]);
            }
#pragma unroll
            for (int q2 = 0; q2 < 8; q2++)
                y[q2] = fmaf(s[q2], sdinv[i * 128 + r0 + q2], y[q2]);
        }
#pragma unroll
        for (int q2 = 0; q2 < 8; q2++)
            g_q[(size_t)(b * NQ + m0 + r0 + q2) * D + h * HD + c] = y[q2] * (1.0f / 3.0f);
    }
}

// ---------------------------------------------------------------------------
// Output projection: out = u @ Wo^T + bo  (u lives in g_q)
__global__ __launch_bounds__(256)
void oproj_kernel(const float* __restrict__ W, const float* __restrict__ bias,
                  float* __restrict__ Out)
{
    __shared__ float sm[128 * 65];
    float (*As)[33] = (float (*)[33])sm;
    float (*Ws)[33] = (float (*)[33])(sm + 128 * 33);
    const int tid = threadIdx.x;
    const int tx = tid & 15, ty = tid >> 4;
    const int m0 = blockIdx.x * 128;
    const int n0 = blockIdx.y * 64;

    float acc[8][4];
#pragma unroll
    for (int i = 0; i < 8; i++)
#pragma unroll
        for (int j = 0; j < 4; j++) acc[i][j] = 0.0f;

    const int lr = tid >> 3, lk = (tid & 7) << 2;
    for (int k0 = 0; k0 < D; k0 += 32) {
#pragma unroll
        for (int it = 0; it < 4; it++) {
            float4 v = *(const float4*)(g_q + (size_t)(m0 + lr + it * 32) * D + k0 + lk);
            float* p = &As[lr + it * 32][lk];
            p[0] = v.x; p[1] = v.y; p[2] = v.z; p[3] = v.w;
        }
#pragma unroll
        for (int it = 0; it < 2; it++) {
            float4 v = *(const float4*)(W + (size_t)(n0 + lr + it * 32) * D + k0 + lk);
            float* p = &Ws[lr + it * 32][lk];
            p[0] = v.x; p[1] = v.y; p[2] = v.z; p[3] = v.w;
        }
        __syncthreads();
#pragma unroll
        for (int kk = 0; kk < 32; kk++) {
            float a[8], bb[4];
#pragma unroll
            for (int i = 0; i < 8; i++) a[i] = As[ty + 16 * i][kk];
#pragma unroll
            for (int j = 0; j < 4; j++) bb[j] = Ws[tx + 16 * j][kk];
#pragma unroll
            for (int i = 0; i < 8; i++)
#pragma unroll
                for (int j = 0; j < 4; j++) acc[i][j] = fmaf(a[i], bb[j], acc[i][j]);
        }
        __syncthreads();
    }

    float (*Cs)[65] = (float (*)[65])sm;
#pragma unroll
    for (int j = 0; j < 4; j++) {
        float bv = bias[n0 + tx + 16 * j];
#pragma unroll
        for (int i = 0; i < 8; i++) Cs[ty + 16 * i][tx + 16 * j] = acc[i][j] + bv;
    }
    __syncthreads();
    const int c = tid & 63, rg = tid >> 6;
    for (int r = rg; r < 128; r += 4)
        Out[(size_t)(m0 + r) * D + n0 + c] = Cs[r][c];
}

// ---------------------------------------------------------------------------
extern "C" void kernel_launch(void* const* d_in, const int* in_sizes, int n_in,
                              void* d_out, int out_size)
{
    (void)in_sizes; (void)n_in; (void)out_size;
    const float* x    = (const float*)d_in[0];
    const float* emb0 = (const float*)d_in[1];
    const float* emb1 = (const float*)d_in[2];
    const float* emb2 = (const float*)d_in[3];
    const float* Wq   = (const float*)d_in[4];
    const float* bq   = (const float*)d_in[5];
    const float* Wk   = (const float*)d_in[6];
    const float* bk   = (const float*)d_in[7];
    const float* Wv   = (const float*)d_in[8];
    const float* bv   = (const float*)d_in[9];
    const float* Wo   = (const float*)d_in[10];
    const float* bo   = (const float*)d_in[11];
    const void* m0 = d_in[12];
    const void* m1 = d_in[13];
    const void* m2 = d_in[14];
    float* out = (float*)d_out;

    cudaFuncSetAttribute(kvproj_kernel,  cudaFuncAttributeMaxDynamicSharedMemorySize, 16640 * 4);
    cudaFuncSetAttribute(combine_kernel, cudaFuncAttributeMaxDynamicSharedMemorySize, 21056 * 4);

    zero_kernel<<<1536, 256>>>((const unsigned int*)m0);
    qproj_kernel<<<dim3(MQ / 128, D / 64), 256>>>(x, Wq, bq);
    kvproj_kernel<<<dim3(NKV / 128, NH, NI_ * B_), 256, 16640 * 4>>>(
        emb0, emb1, emb2, Wk, bk, Wv, bv, m0, m1, m2);
    combine_kernel<<<dim3(NQ / 128, NH, B_), 256, 21056 * 4>>>();
    oproj_kernel<<<dim3(MQ / 128, D / 64), 256>>>(Wo, bo, out);
}

// round 10
// speedup vs baseline: 1.0045x; 1.0045x over previous
#include <cuda_runtime.h>

#define D     512
#define NH    8
#define HD    64
#define NI_   3
#define B_    4
#define NQ    8192
#define NKV   4096
#define MQ    (B_ * NQ)   // 32768

// Scratch (static device arrays; no allocation at runtime).
__device__ float g_q[MQ * D];                    // q, overwritten in-place with u by combine
__device__ float g_kv[NI_ * B_ * NH * HD * HD];  // per (i,b,h) 64x64 kv matrices
__device__ float g_ksum[NI_ * B_ * NH * HD];     // per (i,b,h) 64-vector k_sum
__device__ int   g_mask_u8;                      // 1 if masks are byte-packed bools

// ---------------------------------------------------------------------------
// Zero accumulators + detect mask encoding (word-sized int32/float32 vs uint8).
__global__ void zero_kernel(const unsigned int* __restrict__ mask_words) {
    int idx = blockIdx.x * blockDim.x + threadIdx.x;
    if (idx < NI_ * B_ * NH * HD * HD) g_kv[idx] = 0.0f;
    if (idx < NI_ * B_ * NH * HD)      g_ksum[idx] = 0.0f;
    if (blockIdx.x == 0 && threadIdx.x == 0) {
        // If masks were widened to int32 (0/1) or float32 (0.0/1.0), every
        // 32-bit word is 0, 1, or 0x3F800000. Byte-packed random bools make
        // other word values with overwhelming probability.
        int u8 = 0;
        for (int i = 0; i < 1024; i++) {
            unsigned w = mask_words[i];
            if (w != 0u && w != 1u && w != 0x3F800000u) { u8 = 1; break; }
        }
        g_mask_u8 = u8;
    }
}

// ---------------------------------------------------------------------------
// Q projection: C[m, n0+c] = sum_k x[m,k] * Wq[n0+c,k] + bq, then rowwise
// softmax over the 64 columns of the head (one head == one 64-col tile).
__global__ __launch_bounds__(256)
void qproj_kernel(const float* __restrict__ A, const float* __restrict__ W,
                  const float* __restrict__ bias)
{
    __shared__ float sm[128 * 65];                    // 33.3 KB, reused by epilogue
    float (*As)[33] = (float (*)[33])sm;              // [128][33]
    float (*Ws)[33] = (float (*)[33])(sm + 128 * 33); // [64][33]
    const int tid = threadIdx.x;
    const int tx = tid & 15, ty = tid >> 4;
    const int m0 = blockIdx.x * 128;
    const int n0 = blockIdx.y * 64;

    float acc[8][4];
#pragma unroll
    for (int i = 0; i < 8; i++)
#pragma unroll
        for (int j = 0; j < 4; j++) acc[i][j] = 0.0f;

    const int lr = tid >> 3;          // 0..31
    const int lk = (tid & 7) << 2;    // 0..28 step 4
    for (int k0 = 0; k0 < D; k0 += 32) {
#pragma unroll
        for (int it = 0; it < 4; it++) {
            float4 v = *(const float4*)(A + (size_t)(m0 + lr + it * 32) * D + k0 + lk);
            float* p = &As[lr + it * 32][lk];
            p[0] = v.x; p[1] = v.y; p[2] = v.z; p[3] = v.w;
        }
#pragma unroll
        for (int it = 0; it < 2; it++) {
            float4 v = *(const float4*)(W + (size_t)(n0 + lr + it * 32) * D + k0 + lk);
            float* p = &Ws[lr + it * 32][lk];
            p[0] = v.x; p[1] = v.y; p[2] = v.z; p[3] = v.w;
        }
        __syncthreads();
#pragma unroll
        for (int kk = 0; kk < 32; kk++) {
            float a[8], bb[4];
#pragma unroll
            for (int i = 0; i < 8; i++) a[i] = As[ty + 16 * i][kk];
#pragma unroll
            for (int j = 0; j < 4; j++) bb[j] = Ws[tx + 16 * j][kk];
#pragma unroll
            for (int i = 0; i < 8; i++)
#pragma unroll
                for (int j = 0; j < 4; j++) acc[i][j] = fmaf(a[i], bb[j], acc[i][j]);
        }
        __syncthreads();
    }

    float (*Cs)[65] = (float (*)[65])sm;
#pragma unroll
    for (int j = 0; j < 4; j++) {
        float bv = bias[n0 + tx + 16 * j];
#pragma unroll
        for (int i = 0; i < 8; i++) Cs[ty + 16 * i][tx + 16 * j] = acc[i][j] + bv;
    }
    __syncthreads();

    const int warp = tid >> 5, lane = tid & 31;
    for (int r = warp; r < 128; r += 8) {
        float v0 = Cs[r][lane], v1 = Cs[r][lane + 32];
        float mx = fmaxf(v0, v1);
#pragma unroll
        for (int o = 16; o; o >>= 1) mx = fmaxf(mx, __shfl_xor_sync(0xffffffffu, mx, o));
        float e0 = __expf(v0 - mx), e1 = __expf(v1 - mx);
        float s = e0 + e1;
#pragma unroll
        for (int o = 16; o; o >>= 1) s += __shfl_xor_sync(0xffffffffu, s, o);
        float inv = 1.0f / s;
        size_t base = (size_t)(m0 + r) * D + n0;
        g_q[base + lane]      = e0 * inv;
        g_q[base + lane + 32] = e1 * inv;
    }
}

// ---------------------------------------------------------------------------
// K/V projection for one (i, b, head, 128-row tile):
//  - GEMM: Ck[128,64], Cv[128,64]
//  - softmax rows of Ck, zero masked rows
//  - atomically accumulate k_sum (col sums) and kv = Ck^T @ Cv
// k and v are never written to global memory.
__global__ __launch_bounds__(256)
void kvproj_kernel(const float* __restrict__ emb0, const float* __restrict__ emb1,
                   const float* __restrict__ emb2,
                   const float* __restrict__ Wk, const float* __restrict__ bk,
                   const float* __restrict__ Wv, const float* __restrict__ bv,
                   const void* __restrict__ mask0,
                   const void* __restrict__ mask1,
                   const void* __restrict__ mask2)
{
    extern __shared__ float sm[];                     // 66560 B dynamic
    float (*As)[33] = (float (*)[33])sm;              // [128][33]
    float (*Ws)[33] = (float (*)[33])(sm + 128 * 33); // [128][33]

    const int tid = threadIdx.x;
    const int tx = tid & 15, ty = tid >> 4;
    const int s0 = blockIdx.x * 128;
    const int h  = blockIdx.y;
    const int z  = blockIdx.z;
    const int ii = z >> 2;        // input index 0..2  (B_=4)
    const int b  = z & 3;

    const float* emb = (ii == 0) ? emb0 : (ii == 1) ? emb1 : emb2;
    const void* mask = (ii == 0) ? mask0 : (ii == 1) ? mask1 : mask2;
    const float* A   = emb + (size_t)b * NKV * D;
    const float* Wkh = Wk + (size_t)ii * D * D + (size_t)h * HD * D;
    const float* Wvh = Wv + (size_t)ii * D * D + (size_t)h * HD * D;
    const float* bkh = bk + ii * D + h * HD;
    const float* bvh = bv + ii * D + h * HD;
    const int mask_u8 = g_mask_u8;

    float acc[8][8];
#pragma unroll
    for (int i = 0; i < 8; i++)
#pragma unroll
        for (int j = 0; j < 8; j++) acc[i][j] = 0.0f;

    const int lr = tid >> 3, lk = (tid & 7) << 2;
    for (int k0 = 0; k0 < D; k0 += 32) {
#pragma unroll
        for (int it = 0; it < 4; it++) {
            float4 v = *(const float4*)(A + (size_t)(s0 + lr + it * 32) * D + k0 + lk);
            float* p = &As[lr + it * 32][lk];
            p[0] = v.x; p[1] = v.y; p[2] = v.z; p[3] = v.w;
        }
#pragma unroll
        for (int it = 0; it < 4; it++) {
            int n = lr + it * 32;  // 0..127 : 0-63 -> Wk rows, 64-127 -> Wv rows
            const float* Wp = (n < 64) ? (Wkh + (size_t)n * D) : (Wvh + (size_t)(n - 64) * D);
            float4 v = *(const float4*)(Wp + k0 + lk);
            float* p = &Ws[n][lk];
            p[0] = v.x; p[1] = v.y; p[2] = v.z; p[3] = v.w;
        }
        __syncthreads();
#pragma unroll
        for (int kk = 0; kk < 32; kk++) {
            float a[8], bb[8];
#pragma unroll
            for (int i = 0; i < 8; i++) a[i] = As[ty + 16 * i][kk];
#pragma unroll
            for (int j = 0; j < 8; j++) bb[j] = Ws[tx + 16 * j][kk];
#pragma unroll
            for (int i = 0; i < 8; i++)
#pragma unroll
                for (int j = 0; j < 8; j++) acc[i][j] = fmaf(a[i], bb[j], acc[i][j]);
        }
        __syncthreads();
    }

    // Epilogue staging: Ks [128][65] at 0, Vs [128][65] at +8320 floats
    float (*Ks)[65] = (float (*)[65])sm;
    float (*Vs)[65] = (float (*)[65])(sm + 8320);
#pragma unroll
    for (int j = 0; j < 8; j++) {
        int c = tx + 16 * j;       // 0..127
        float bvl = (c < 64) ? bkh[c] : bvh[c - 64];
#pragma unroll
        for (int i = 0; i < 8; i++) {
            float val = acc[i][j] + bvl;
            if (c < 64) Ks[ty + 16 * i][c]      = val;
            else        Vs[ty + 16 * i][c - 64] = val;
        }
    }
    __syncthreads();

    // Per-row softmax on Ks, then zero masked rows (softmax then mask, per reference)
    const int warp = tid >> 5, lane = tid & 31;
    for (int r = warp; r < 128; r += 8) {
        float v0 = Ks[r][lane], v1 = Ks[r][lane + 32];
        float mx = fmaxf(v0, v1);
#pragma unroll
        for (int o = 16; o; o >>= 1) mx = fmaxf(mx, __shfl_xor_sync(0xffffffffu, mx, o));
        float e0 = __expf(v0 - mx), e1 = __expf(v1 - mx);
        float s = e0 + e1;
#pragma unroll
        for (int o = 16; o; o >>= 1) s += __shfl_xor_sync(0xffffffffu, s, o);
        float inv = 1.0f / s;
        size_t midx = (size_t)b * NKV + s0 + r;
        bool keep;
        if (mask_u8) keep = ((const unsigned char*)mask)[midx] != 0;
        else         keep = ((const unsigned int*)mask)[midx]  != 0u;  // int32 or fp32 0/1
        float mval = keep ? inv : 0.0f;
        Ks[r][lane]      = e0 * mval;
        Ks[r][lane + 32] = e1 * mval;
    }
    __syncthreads();

    // k_sum partial (4 partial sums per column, atomically merged)
    {
        int c = tid & 63, qg = tid >> 6;
        float s = 0.0f;
#pragma unroll
        for (int r = 0; r < 32; r++) s += Ks[qg * 32 + r][c];
        atomicAdd(&g_ksum[((ii * B_ + b) * NH + h) * HD + c], s);
    }

    // kv partial: P[d][e] = sum_r Ks[r][d] * Vs[r][e], 4x4 per thread
    {
        float p[4][4];
#pragma unroll
        for (int a2 = 0; a2 < 4; a2++)
#pragma unroll
            for (int b2 = 0; b2 < 4; b2++) p[a2][b2] = 0.0f;
        for (int r = 0; r < 128; r++) {
            float kd[4], ve[4];
#pragma unroll
            for (int a2 = 0; a2 < 4; a2++) kd[a2] = Ks[r][ty + 16 * a2];
#pragma unroll
            for (int b2 = 0; b2 < 4; b2++) ve[b2] = Vs[r][tx + 16 * b2];
#pragma unroll
            for (int a2 = 0; a2 < 4; a2++)
#pragma unroll
                for (int b2 = 0; b2 < 4; b2++) p[a2][b2] = fmaf(kd[a2], ve[b2], p[a2][b2]);
        }
        float* kvp = g_kv + (size_t)((ii * B_ + b) * NH + h) * HD * HD;
#pragma unroll
        for (int a2 = 0; a2 < 4; a2++)
#pragma unroll
            for (int b2 = 0; b2 < 4; b2++)
                atomicAdd(&kvp[(ty + 16 * a2) * HD + tx + 16 * b2], p[a2][b2]);
    }
}

// ---------------------------------------------------------------------------
// Combine: u = (q + sum_i (q @ kv_i) * d_inv_i) / NI, in-place over g_q.
__global__ __launch_bounds__(256)
void combine_kernel()
{
    extern __shared__ float sm[];        // 84224 B dynamic
    float* kvs   = sm;                   // 3*64*64 = 12288
    float* qs    = sm + 12288;           // 128*64  = 8192
    float* ksums = sm + 20480;           // 3*64    = 192
    float* sdinv = sm + 20672;           // 3*128   = 384
    const int tid = threadIdx.x;
    const int m0 = blockIdx.x * 128;
    const int h  = blockIdx.y;
    const int b  = blockIdx.z;

    for (int idx = tid; idx < 3072; idx += 256) {
        int i = idx >> 10;
        int off = (idx & 1023) << 2;
        float4 v = *(const float4*)(g_kv + (size_t)((i * B_ + b) * NH + h) * 4096 + off);
        float* p = kvs + i * 4096 + off;
        p[0] = v.x; p[1] = v.y; p[2] = v.z; p[3] = v.w;
    }
    for (int idx = tid; idx < 2048; idx += 256) {
        int r = idx >> 4;
        int c4 = (idx & 15) << 2;
        float4 v = *(const float4*)(g_q + (size_t)(b * NQ + m0 + r) * D + h * HD + c4);
        float* p = qs + r * 64 + c4;
        p[0] = v.x; p[1] = v.y; p[2] = v.z; p[3] = v.w;
    }
    if (tid < 192) {
        int i = tid >> 6, c = tid & 63;
        ksums[tid] = g_ksum[((i * B_ + b) * NH + h) * HD + c];
    }
    __syncthreads();

    for (int idx = tid; idx < 384; idx += 256) {
        int r = idx & 127, i = idx >> 7;
        float s = 0.0f;
#pragma unroll
        for (int d = 0; d < 64; d++) s += qs[r * 64 + d] * ksums[i * 64 + d];
        sdinv[i * 128 + r] = 1.0f / s;
    }
    __syncthreads();

    const int c  = tid & 63;
    const int rg = tid >> 6;
    for (int rc = 0; rc < 32; rc += 8) {
        const int r0 = rg * 32 + rc;
        float y[8];
#pragma unroll
        for (int q2 = 0; q2 < 8; q2++) y[q2] = qs[(r0 + q2) * 64 + c];
#pragma unroll
        for (int i = 0; i < 3; i++) {
            float s[8];
#pragma unroll
            for (int q2 = 0; q2 < 8; q2++) s[q2] = 0.0f;
            for (int d = 0; d < 64; d++) {
                float kvv = kvs[i * 4096 + d * 64 + c];
#pragma unroll
                for (int q2 = 0; q2 < 8; q2++)
                    s[q2] = fmaf(qs[(r0 + q2) * 64 + d], kvv, s[q2]);
            }
#pragma unroll
            for (int q2 = 0; q2 < 8; q2++)
                y[q2] = fmaf(s[q2], sdinv[i * 128 + r0 + q2], y[q2]);
        }
#pragma unroll
        for (int q2 = 0; q2 < 8; q2++)
            g_q[(size_t)(b * NQ + m0 + r0 + q2) * D + h * HD + c] = y[q2] * (1.0f / 3.0f);
    }
}

// ---------------------------------------------------------------------------
// Output projection: out = u @ Wo^T + bo  (u lives in g_q)
__global__ __launch_bounds__(256)
void oproj_kernel(const float* __restrict__ W, const float* __restrict__ bias,
                  float* __restrict__ Out)
{
    __shared__ float sm[128 * 65];
    float (*As)[33] = (float (*)[33])sm;
    float (*Ws)[33] = (float (*)[33])(sm + 128 * 33);
    const int tid = threadIdx.x;
    const int tx = tid & 15, ty = tid >> 4;
    const int m0 = blockIdx.x * 128;
    const int n0 = blockIdx.y * 64;

    float acc[8][4];
#pragma unroll
    for (int i = 0; i < 8; i++)
#pragma unroll
        for (int j = 0; j < 4; j++) acc[i][j] = 0.0f;

    const int lr = tid >> 3, lk = (tid & 7) << 2;
    for (int k0 = 0; k0 < D; k0 += 32) {
#pragma unroll
        for (int it = 0; it < 4; it++) {
            float4 v = *(const float4*)(g_q + (size_t)(m0 + lr + it * 32) * D + k0 + lk);
            float* p = &As[lr + it * 32][lk];
            p[0] = v.x; p[1] = v.y; p[2] = v.z; p[3] = v.w;
        }
#pragma unroll
        for (int it = 0; it < 2; it++) {
            float4 v = *(const float4*)(W + (size_t)(n0 + lr + it * 32) * D + k0 + lk);
            float* p = &Ws[lr + it * 32][lk];
            p[0] = v.x; p[1] = v.y; p[2] = v.z; p[3] = v.w;
        }
        __syncthreads();
#pragma unroll
        for (int kk = 0; kk < 32; kk++) {
            float a[8], bb[4];
#pragma unroll
            for (int i = 0; i < 8; i++) a[i] = As[ty + 16 * i][kk];
#pragma unroll
            for (int j = 0; j < 4; j++) bb[j] = Ws[tx + 16 * j][kk];
#pragma unroll
            for (int i = 0; i < 8; i++)
#pragma unroll
                for (int j = 0; j < 4; j++) acc[i][j] = fmaf(a[i], bb[j], acc[i][j]);
        }
        __syncthreads();
    }

    float (*Cs)[65] = (float (*)[65])sm;
#pragma unroll
    for (int j = 0; j < 4; j++) {
        float bv = bias[n0 + tx + 16 * j];
#pragma unroll
        for (int i = 0; i < 8; i++) Cs[ty + 16 * i][tx + 16 * j] = acc[i][j] + bv;
    }
    __syncthreads();
    const int c = tid & 63, rg = tid >> 6;
    for (int r = rg; r < 128; r += 4)
        Out[(size_t)(m0 + r) * D + n0 + c] = Cs[r][c];
}

// ---------------------------------------------------------------------------
extern "C" void kernel_launch(void* const* d_in, const int* in_sizes, int n_in,
                              void* d_out, int out_size)
{
    (void)in_sizes; (void)n_in; (void)out_size;
    const float* x    = (const float*)d_in[0];
    const float* emb0 = (const float*)d_in[1];
    const float* emb1 = (const float*)d_in[2];
    const float* emb2 = (const float*)d_in[3];
    const float* Wq   = (const float*)d_in[4];
    const float* bq   = (const float*)d_in[5];
    const float* Wk   = (const float*)d_in[6];
    const float* bk   = (const float*)d_in[7];
    const float* Wv   = (const float*)d_in[8];
    const float* bv   = (const float*)d_in[9];
    const float* Wo   = (const float*)d_in[10];
    const float* bo   = (const float*)d_in[11];
    const void* m0 = d_in[12];
    const void* m1 = d_in[13];
    const void* m2 = d_in[14];
    float* out = (float*)d_out;

    cudaFuncSetAttribute(kvproj_kernel,  cudaFuncAttributeMaxDynamicSharedMemorySize, 16640 * 4);
    cudaFuncSetAttribute(combine_kernel, cudaFuncAttributeMaxDynamicSharedMemorySize, 21056 * 4);

    zero_kernel<<<1536, 256>>>((const unsigned int*)m0);
    qproj_kernel<<<dim3(MQ / 128, D / 64), 256>>>(x, Wq, bq);
    kvproj_kernel<<<dim3(NKV / 128, NH, NI_ * B_), 256, 16640 * 4>>>(
        emb0, emb1, emb2, Wk, bk, Wv, bv, m0, m1, m2);
    combine_kernel<<<dim3(NQ / 128, NH, B_), 256, 21056 * 4>>>();
    oproj_kernel<<<dim3(MQ / 128, D / 64), 256>>>(Wo, bo, out);
}

// round 17
// speedup vs baseline: 2.0422x; 2.0330x over previous
#include <cuda_runtime.h>
#include <cstdint>

#define D     512
#define NH    8
#define HD    64
#define NI_   3
#define B_    4
#define NQ    8192
#define NKV   4096
#define MQ    (B_ * NQ)   // 32768

// Scratch (static device arrays; no allocation at runtime).
__device__ float g_q[MQ * D];                    // q, overwritten in-place with u by combine
__device__ float g_kv[NI_ * B_ * NH * HD * HD];  // per (i,b,h) 64x64 kv matrices
__device__ float g_ksum[NI_ * B_ * NH * HD];     // per (i,b,h) 64-vector k_sum
__device__ int   g_mask_u8;                      // 1 if masks are byte-packed bools

// ---------------------------------------------------------------------------
// mma.sync tf32 helpers (sm_80+ baseline ISA — valid on sm_103 non-'a' target)
// ---------------------------------------------------------------------------
__device__ __forceinline__ uint32_t f2tf(float f) {
    uint32_t u;
    asm("cvt.rna.tf32.f32 %0, %1;" : "=r"(u) : "f"(f));
    return u;
}
__device__ __forceinline__ void mma_tf32(float* c, const uint32_t* a, const uint32_t* b) {
    asm volatile(
        "mma.sync.aligned.m16n8k8.row.col.f32.tf32.tf32.f32 "
        "{%0,%1,%2,%3}, {%4,%5,%6,%7}, {%8,%9}, {%0,%1,%2,%3};"
        : "+f"(c[0]), "+f"(c[1]), "+f"(c[2]), "+f"(c[3])
        : "r"(a[0]), "r"(a[1]), "r"(a[2]), "r"(a[3]), "r"(b[0]), "r"(b[1]));
}

#define ASR   36              // SMEM row stride (floats); 36 mod 32 = 4 -> conflict-free frags
#define STG   (128 * ASR)     // floats per stage (128 rows x 32 cols padded)
#define NCH   16              // K=512 / 32
#define SMEM_GEMM (4 * STG * 4)   // 2 stages A + 2 stages B = 73728 bytes

// Shared mainloop: prologue chunk0, then LDG-prefetch / compute / STS / bar.
// A fragment register order (PTX ISA m16n8k8 tf32):
//   a0=(row,k) a1=(row+8,k) a2=(row,k+4) a3=(row+8,k+4), row=lane>>2, k=lane&3.
#define GEMM_MAINLOOP(APTR_EXPR, BPTR_EXPR) \
    { /* prologue: chunk 0 -> stage 0 */ \
        _Pragma("unroll") \
        for (int it = 0; it < 4; it++) { \
            int idx = tid + it * 256; int r = idx >> 3, cg = idx & 7; \
            const float* _ap = (APTR_EXPR); \
            const float* _bp = (BPTR_EXPR); \
            float4 va = *(const float4*)(_ap + cg * 4); \
            float4 vb = *(const float4*)(_bp + cg * 4); \
            uint4 ua = make_uint4(f2tf(va.x), f2tf(va.y), f2tf(va.z), f2tf(va.w)); \
            uint4 ub = make_uint4(f2tf(vb.x), f2tf(vb.y), f2tf(vb.z), f2tf(vb.w)); \
            *(uint4*)(sA + r * ASR + cg * 4) = ua; \
            *(uint4*)(sB + r * ASR + cg * 4) = ub; \
        } \
    } \
    __syncthreads(); \
    for (int kc = 0; kc < NCH; kc++) { \
        int cur = kc & 1; \
        float4 pa[4], pb[4]; \
        if (kc < NCH - 1) { \
            int k0 = (kc + 1) * 32; \
            _Pragma("unroll") \
            for (int it = 0; it < 4; it++) { \
                int idx = tid + it * 256; int r = idx >> 3, cg = idx & 7; \
                const float* _ap = (APTR_EXPR); \
                const float* _bp = (BPTR_EXPR); \
                pa[it] = *(const float4*)(_ap + k0 + cg * 4); \
                pb[it] = *(const float4*)(_bp + k0 + cg * 4); \
            } \
        } \
        { \
            const uint32_t* Au = (const uint32_t*)(sA + cur * STG); \
            const uint32_t* Bu = (const uint32_t*)(sB + cur * STG); \
            const int ar = warpM * 64 + (lane >> 2), ac = lane & 3; \
            const int bn = warpN * 32 + (lane >> 2), bkk = lane & 3; \
            _Pragma("unroll") \
            for (int k8 = 0; k8 < 4; k8++) { \
                int kb = k8 * 8; \
                uint32_t af[4][4], bf[4][2]; \
                _Pragma("unroll") \
                for (int mt = 0; mt < 4; mt++) { \
                    const uint32_t* p0 = Au + (ar + mt * 16) * ASR + kb + ac; \
                    const uint32_t* p1 = p0 + 8 * ASR; \
                    af[mt][0] = p0[0]; af[mt][1] = p1[0]; \
                    af[mt][2] = p0[4]; af[mt][3] = p1[4]; \
                } \
                _Pragma("unroll") \
                for (int nt = 0; nt < 4; nt++) { \
                    const uint32_t* p = Bu + (bn + nt * 8) * ASR + kb + bkk; \
                    bf[nt][0] = p[0]; bf[nt][1] = p[4]; \
                } \
                _Pragma("unroll") \
                for (int mt = 0; mt < 4; mt++) \
                    _Pragma("unroll") \
                    for (int nt = 0; nt < 4; nt++) \
                        mma_tf32(acc[mt][nt], af[mt], bf[nt]); \
            } \
        } \
        if (kc < NCH - 1) { \
            float* dA = sA + (cur ^ 1) * STG; \
            float* dB = sB + (cur ^ 1) * STG; \
            _Pragma("unroll") \
            for (int it = 0; it < 4; it++) { \
                int idx = tid + it * 256; int r = idx >> 3, cg = idx & 7; \
                uint4 ua = make_uint4(f2tf(pa[it].x), f2tf(pa[it].y), f2tf(pa[it].z), f2tf(pa[it].w)); \
                uint4 ub = make_uint4(f2tf(pb[it].x), f2tf(pb[it].y), f2tf(pb[it].z), f2tf(pb[it].w)); \
                *(uint4*)(dA + r * ASR + cg * 4) = ua; \
                *(uint4*)(dB + r * ASR + cg * 4) = ub; \
            } \
        } \
        __syncthreads(); \
    }

// ---------------------------------------------------------------------------
// Zero accumulators + detect mask encoding (word-sized int32/float32 vs uint8).
__global__ void zero_kernel(const unsigned int* __restrict__ mask_words) {
    int idx = blockIdx.x * blockDim.x + threadIdx.x;
    if (idx < NI_ * B_ * NH * HD * HD) g_kv[idx] = 0.0f;
    if (idx < NI_ * B_ * NH * HD)      g_ksum[idx] = 0.0f;
    if (blockIdx.x == 0 && threadIdx.x == 0) {
        int u8 = 0;
        for (int i = 0; i < 1024; i++) {
            unsigned w = mask_words[i];
            if (w != 0u && w != 1u && w != 0x3F800000u) { u8 = 1; break; }
        }
        g_mask_u8 = u8;
    }
}

// ---------------------------------------------------------------------------
// Q projection (tf32 mma): C = x·Wq^T + bq, per-head softmax -> g_q.
// Block: 128 rows x 128 cols (= 2 heads). Grid (MQ/128, 4).
__global__ __launch_bounds__(256)
void qproj_mma(const float* __restrict__ A, const float* __restrict__ W,
               const float* __restrict__ bias)
{
    extern __shared__ float sm[];
    float* sA = sm;
    float* sB = sm + 2 * STG;
    const int tid = threadIdx.x, lane = tid & 31, wid = tid >> 5;
    const int warpM = wid >> 2, warpN = wid & 3;
    const int m0 = blockIdx.x * 128, n0 = blockIdx.y * 128;
    const float* Ab = A + (size_t)m0 * D;
    const float* Bb = W + (size_t)n0 * D;

    float breg[4][2];
#pragma unroll
    for (int nt = 0; nt < 4; nt++) {
        int c = n0 + warpN * 32 + nt * 8 + (lane & 3) * 2;
        breg[nt][0] = bias[c]; breg[nt][1] = bias[c + 1];
    }

    float acc[4][4][4];
#pragma unroll
    for (int mt = 0; mt < 4; mt++)
#pragma unroll
        for (int nt = 0; nt < 4; nt++)
#pragma unroll
            for (int q = 0; q < 4; q++) acc[mt][nt][q] = 0.0f;

    GEMM_MAINLOOP(Ab + (size_t)r * D, Bb + (size_t)r * D)

    // Epilogue: stage to Cs (stride 132, overlays sA/sB), bias added here.
    float (*Cs)[132] = (float (*)[132])sm;
#pragma unroll
    for (int mt = 0; mt < 4; mt++) {
        int r = warpM * 64 + mt * 16 + (lane >> 2);
#pragma unroll
        for (int nt = 0; nt < 4; nt++) {
            int c = warpN * 32 + nt * 8 + (lane & 3) * 2;
            Cs[r][c]         = acc[mt][nt][0] + breg[nt][0];
            Cs[r][c + 1]     = acc[mt][nt][1] + breg[nt][1];
            Cs[r + 8][c]     = acc[mt][nt][2] + breg[nt][0];
            Cs[r + 8][c + 1] = acc[mt][nt][3] + breg[nt][1];
        }
    }
    __syncthreads();

    // Per-row softmax over each 64-col head (2 heads per block).
    for (int r = wid; r < 128; r += 8) {
#pragma unroll
        for (int hl = 0; hl < 2; hl++) {
            int cb = hl * 64;
            float v0 = Cs[r][cb + lane], v1 = Cs[r][cb + lane + 32];
            float mx = fmaxf(v0, v1);
#pragma unroll
            for (int o = 16; o; o >>= 1) mx = fmaxf(mx, __shfl_xor_sync(0xffffffffu, mx, o));
            float e0 = __expf(v0 - mx), e1 = __expf(v1 - mx);
            float s = e0 + e1;
#pragma unroll
            for (int o = 16; o; o >>= 1) s += __shfl_xor_sync(0xffffffffu, s, o);
            float inv = 1.0f / s;
            size_t base = (size_t)(m0 + r) * D + n0 + cb;
            g_q[base + lane]      = e0 * inv;
            g_q[base + lane + 32] = e1 * inv;
        }
    }
}

// ---------------------------------------------------------------------------
// K/V projection (tf32 mma) for ONE head: N cols 0..63 = K-proj, 64..127 = V-proj.
// Epilogue: softmax+mask K rows, accumulate ksum + kv = K^T V with atomics.
// Grid (NKV/128, NH, NI_*B_).
__global__ __launch_bounds__(256)
void kvproj_mma(const float* __restrict__ emb0, const float* __restrict__ emb1,
                const float* __restrict__ emb2,
                const float* __restrict__ Wk, const float* __restrict__ bk,
                const float* __restrict__ Wv, const float* __restrict__ bv,
                const void* __restrict__ mask0, const void* __restrict__ mask1,
                const void* __restrict__ mask2)
{
    extern __shared__ float sm[];
    float* sA = sm;
    float* sB = sm + 2 * STG;
    const int tid = threadIdx.x, lane = tid & 31, wid = tid >> 5;
    const int warpM = wid >> 2, warpN = wid & 3;
    const int s0 = blockIdx.x * 128;
    const int h  = blockIdx.y;
    const int z  = blockIdx.z;
    const int ii = z >> 2, b = z & 3;

    const float* emb = (ii == 0) ? emb0 : (ii == 1) ? emb1 : emb2;
    const void* mask = (ii == 0) ? mask0 : (ii == 1) ? mask1 : mask2;
    const float* Ab  = emb + (size_t)b * NKV * D + (size_t)s0 * D;
    const float* Wkh = Wk + (size_t)ii * D * D + (size_t)h * HD * D;
    const float* Wvh = Wv + (size_t)ii * D * D + (size_t)h * HD * D;
    const float* bkh = bk + ii * D + h * HD;
    const float* bvh = bv + ii * D + h * HD;

    float breg[4][2];
#pragma unroll
    for (int nt = 0; nt < 4; nt++) {
        int c = warpN * 32 + nt * 8 + (lane & 3) * 2;
        breg[nt][0] = (c < 64)     ? bkh[c]     : bvh[c - 64];
        breg[nt][1] = (c + 1 < 64) ? bkh[c + 1] : bvh[c + 1 - 64];
    }

    float acc[4][4][4];
#pragma unroll
    for (int mt = 0; mt < 4; mt++)
#pragma unroll
        for (int nt = 0; nt < 4; nt++)
#pragma unroll
            for (int q = 0; q < 4; q++) acc[mt][nt][q] = 0.0f;

    GEMM_MAINLOOP(Ab + (size_t)r * D,
                  (r < 64 ? Wkh + (size_t)r * D : Wvh + (size_t)(r - 64) * D))

    // Epilogue staging: Ks [128][65] at 0, Vs [128][65] at +8320 (overlays sA/sB)
    float (*Ks)[65] = (float (*)[65])sm;
    float (*Vs)[65] = (float (*)[65])(sm + 8320);
#pragma unroll
    for (int mt = 0; mt < 4; mt++) {
        int r = warpM * 64 + mt * 16 + (lane >> 2);
#pragma unroll
        for (int nt = 0; nt < 4; nt++) {
            int c = warpN * 32 + nt * 8 + (lane & 3) * 2;
            float v0 = acc[mt][nt][0] + breg[nt][0];
            float v1 = acc[mt][nt][1] + breg[nt][1];
            float v2 = acc[mt][nt][2] + breg[nt][0];
            float v3 = acc[mt][nt][3] + breg[nt][1];
            if (c < 64) {
                Ks[r][c] = v0;     Ks[r][c + 1] = v1;
                Ks[r + 8][c] = v2; Ks[r + 8][c + 1] = v3;
            } else {
                Vs[r][c - 64] = v0;     Vs[r][c - 63] = v1;
                Vs[r + 8][c - 64] = v2; Vs[r + 8][c - 63] = v3;
            }
        }
    }
    __syncthreads();

    // Per-row softmax on Ks, then zero masked rows (softmax then mask, per ref)
    const int mask_u8 = g_mask_u8;
    for (int r = wid; r < 128; r += 8) {
        float v0 = Ks[r][lane], v1 = Ks[r][lane + 32];
        float mx = fmaxf(v0, v1);
#pragma unroll
        for (int o = 16; o; o >>= 1) mx = fmaxf(mx, __shfl_xor_sync(0xffffffffu, mx, o));
        float e0 = __expf(v0 - mx), e1 = __expf(v1 - mx);
        float s = e0 + e1;
#pragma unroll
        for (int o = 16; o; o >>= 1) s += __shfl_xor_sync(0xffffffffu, s, o);
        float inv = 1.0f / s;
        size_t midx = (size_t)b * NKV + s0 + r;
        bool keep;
        if (mask_u8) keep = ((const unsigned char*)mask)[midx] != 0;
        else         keep = ((const unsigned int*)mask)[midx]  != 0u;
        float mval = keep ? inv : 0.0f;
        Ks[r][lane]      = e0 * mval;
        Ks[r][lane + 32] = e1 * mval;
    }
    __syncthreads();

    // k_sum partial (4 partial sums per column, atomically merged)
    {
        int c = tid & 63, qg = tid >> 6;
        float s = 0.0f;
#pragma unroll
        for (int r = 0; r < 32; r++) s += Ks[qg * 32 + r][c];
        atomicAdd(&g_ksum[((ii * B_ + b) * NH + h) * HD + c], s);
    }

    // kv partial: P[d][e] = sum_r Ks[r][d] * Vs[r][e], 4x4 per thread (16x16 grid)
    {
        const int tx = tid & 15, ty = tid >> 4;
        float p[4][4];
#pragma unroll
        for (int a2 = 0; a2 < 4; a2++)
#pragma unroll
            for (int b2 = 0; b2 < 4; b2++) p[a2][b2] = 0.0f;
        for (int r = 0; r < 128; r++) {
            float kd[4], ve[4];
#pragma unroll
            for (int a2 = 0; a2 < 4; a2++) kd[a2] = Ks[r][ty + 16 * a2];
#pragma unroll
            for (int b2 = 0; b2 < 4; b2++) ve[b2] = Vs[r][tx + 16 * b2];
#pragma unroll
            for (int a2 = 0; a2 < 4; a2++)
#pragma unroll
                for (int b2 = 0; b2 < 4; b2++) p[a2][b2] = fmaf(kd[a2], ve[b2], p[a2][b2]);
        }
        float* kvp = g_kv + (size_t)((ii * B_ + b) * NH + h) * HD * HD;
#pragma unroll
        for (int a2 = 0; a2 < 4; a2++)
#pragma unroll
            for (int b2 = 0; b2 < 4; b2++)
                atomicAdd(&kvp[(ty + 16 * a2) * HD + tx + 16 * b2], p[a2][b2]);
    }
}

// ---------------------------------------------------------------------------
// Output projection (tf32 mma): out = u·Wo^T + bo (u lives in g_q).
// Grid (MQ/128, 4).
__global__ __launch_bounds__(256)
void oproj_mma(const float* __restrict__ W, const float* __restrict__ bias,
               float* __restrict__ Out)
{
    extern __shared__ float sm[];
    float* sA = sm;
    float* sB = sm + 2 * STG;
    const int tid = threadIdx.x, lane = tid & 31, wid = tid >> 5;
    const int warpM = wid >> 2, warpN = wid & 3;
    const int m0 = blockIdx.x * 128, n0 = blockIdx.y * 128;
    const float* Ab = g_q + (size_t)m0 * D;
    const float* Bb = W + (size_t)n0 * D;

    float breg[4][2];
#pragma unroll
    for (int nt = 0; nt < 4; nt++) {
        int c = n0 + warpN * 32 + nt * 8 + (lane & 3) * 2;
        breg[nt][0] = bias[c]; breg[nt][1] = bias[c + 1];
    }

    float acc[4][4][4];
#pragma unroll
    for (int mt = 0; mt < 4; mt++)
#pragma unroll
        for (int nt = 0; nt < 4; nt++)
#pragma unroll
            for (int q = 0; q < 4; q++) acc[mt][nt][q] = 0.0f;

    GEMM_MAINLOOP(Ab + (size_t)r * D, Bb + (size_t)r * D)

    float (*Cs)[132] = (float (*)[132])sm;
#pragma unroll
    for (int mt = 0; mt < 4; mt++) {
        int r = warpM * 64 + mt * 16 + (lane >> 2);
#pragma unroll
        for (int nt = 0; nt < 4; nt++) {
            int c = warpN * 32 + nt * 8 + (lane & 3) * 2;
            Cs[r][c]         = acc[mt][nt][0] + breg[nt][0];
            Cs[r][c + 1]     = acc[mt][nt][1] + breg[nt][1];
            Cs[r + 8][c]     = acc[mt][nt][2] + breg[nt][0];
            Cs[r + 8][c + 1] = acc[mt][nt][3] + breg[nt][1];
        }
    }
    __syncthreads();

#pragma unroll
    for (int it = 0; it < 16; it++) {
        int idx = tid + it * 256;          // 4096 float4 = 128 rows x 32 groups
        int r = idx >> 5, c4 = (idx & 31) * 4;
        float4 o = make_float4(Cs[r][c4], Cs[r][c4 + 1], Cs[r][c4 + 2], Cs[r][c4 + 3]);
        *(float4*)(Out + (size_t)(m0 + r) * D + n0 + c4) = o;
    }
}

// ---------------------------------------------------------------------------
// Combine: u = (q + sum_i (q @ kv_i) * d_inv_i) / NI, in-place over g_q.
// 16x16 thread grid, 8x4 accumulators: 12 LDS per 32 FMA.
__global__ __launch_bounds__(256)
void combine_kernel()
{
    extern __shared__ float sm[];
    float* kvs   = sm;                   // 3*64*64 = 12288  (stride 64)
    float* qs    = sm + 12288;           // 128*65  = 8320   (stride 65)
    float* ksums = sm + 20608;           // 3*64    = 192
    float* sdinv = sm + 20800;           // 3*128   = 384    -> total 21184 floats
    const int tid = threadIdx.x;
    const int m0 = blockIdx.x * 128;
    const int h  = blockIdx.y;
    const int b  = blockIdx.z;

    for (int idx = tid; idx < 3072; idx += 256) {
        int i = idx >> 10;
        int off = (idx & 1023) << 2;
        float4 v = *(const float4*)(g_kv + (size_t)((i * B_ + b) * NH + h) * 4096 + off);
        float* p = kvs + i * 4096 + off;
        p[0] = v.x; p[1] = v.y; p[2] = v.z; p[3] = v.w;
    }
    for (int idx = tid; idx < 2048; idx += 256) {
        int r = idx >> 4;
        int c4 = (idx & 15) << 2;
        float4 v = *(const float4*)(g_q + (size_t)(b * NQ + m0 + r) * D + h * HD + c4);
        float* p = qs + r * 65 + c4;
        p[0] = v.x; p[1] = v.y; p[2] = v.z; p[3] = v.w;   // scalar STS (stride 65)
    }
    if (tid < 192) {
        int i = tid >> 6, c = tid & 63;
        ksums[tid] = g_ksum[((i * B_ + b) * NH + h) * HD + c];
    }
    __syncthreads();

    for (int idx = tid; idx < 384; idx += 256) {
        int r = idx & 127, i = idx >> 7;
        float s = 0.0f;
#pragma unroll
        for (int d = 0; d < 64; d++) s += qs[r * 65 + d] * ksums[i * 64 + d];
        sdinv[i * 128 + r] = 1.0f / s;
    }
    __syncthreads();

    const int tx = tid & 15, ty = tid >> 4;   // rows ty+16i (i 0..7), cols tx+16j (j 0..3)
    float y[8][4];
#pragma unroll
    for (int i = 0; i < 8; i++)
#pragma unroll
        for (int j = 0; j < 4; j++) y[i][j] = qs[(ty + 16 * i) * 65 + tx + 16 * j];

#pragma unroll
    for (int m = 0; m < 3; m++) {
        float s[8][4];
#pragma unroll
        for (int i = 0; i < 8; i++)
#pragma unroll
            for (int j = 0; j < 4; j++) s[i][j] = 0.0f;
        for (int d = 0; d < 64; d++) {
            float a[8], bb[4];
#pragma unroll
            for (int i = 0; i < 8; i++) a[i] = qs[(ty + 16 * i) * 65 + d];
#pragma unroll
            for (int j = 0; j < 4; j++) bb[j] = kvs[m * 4096 + d * 64 + tx + 16 * j];
#pragma unroll
            for (int i = 0; i < 8; i++)
#pragma unroll
                for (int j = 0; j < 4; j++) s[i][j] = fmaf(a[i], bb[j], s[i][j]);
        }
#pragma unroll
        for (int i = 0; i < 8; i++) {
            float di = sdinv[m * 128 + ty + 16 * i];
#pragma unroll
            for (int j = 0; j < 4; j++) y[i][j] = fmaf(s[i][j], di, y[i][j]);
        }
    }
#pragma unroll
    for (int i = 0; i < 8; i++)
#pragma unroll
        for (int j = 0; j < 4; j++)
            g_q[(size_t)(b * NQ + m0 + ty + 16 * i) * D + h * HD + tx + 16 * j] =
                y[i][j] * (1.0f / 3.0f);
}

// ---------------------------------------------------------------------------
extern "C" void kernel_launch(void* const* d_in, const int* in_sizes, int n_in,
                              void* d_out, int out_size)
{
    (void)in_sizes; (void)n_in; (void)out_size;
    const float* x    = (const float*)d_in[0];
    const float* emb0 = (const float*)d_in[1];
    const float* emb1 = (const float*)d_in[2];
    const float* emb2 = (const float*)d_in[3];
    const float* Wq   = (const float*)d_in[4];
    const float* bq   = (const float*)d_in[5];
    const float* Wk   = (const float*)d_in[6];
    const float* bk   = (const float*)d_in[7];
    const float* Wv   = (const float*)d_in[8];
    const float* bv   = (const float*)d_in[9];
    const float* Wo   = (const float*)d_in[10];
    const float* bo   = (const float*)d_in[11];
    const void* m0 = d_in[12];
    const void* m1 = d_in[13];
    const void* m2 = d_in[14];
    float* out = (float*)d_out;

    cudaFuncSetAttribute(qproj_mma,  cudaFuncAttributeMaxDynamicSharedMemorySize, SMEM_GEMM);
    cudaFuncSetAttribute(kvproj_mma, cudaFuncAttributeMaxDynamicSharedMemorySize, SMEM_GEMM);
    cudaFuncSetAttribute(oproj_mma,  cudaFuncAttributeMaxDynamicSharedMemorySize, SMEM_GEMM);
    cudaFuncSetAttribute(combine_kernel, cudaFuncAttributeMaxDynamicSharedMemorySize, 21184 * 4);

    zero_kernel<<<1536, 256>>>((const unsigned int*)m0);
    qproj_mma<<<dim3(MQ / 128, 4), 256, SMEM_GEMM>>>(x, Wq, bq);
    kvproj_mma<<<dim3(NKV / 128, NH, NI_ * B_), 256, SMEM_GEMM>>>(
        emb0, emb1, emb2, Wk, bk, Wv, bv, m0, m1, m2);
    combine_kernel<<<dim3(NQ / 128, NH, B_), 256, 21184 * 4>>>();
    oproj_mma<<<dim3(MQ / 128, 4), 256, SMEM_GEMM>>>(Wo, bo, out);
}